// round 15
// baseline (speedup 1.0000x reference)
#include <cuda_runtime.h>
#include <cuda_fp16.h>
#include <math.h>
#include <stdint.h>

#define NNODES 10000
#define KNBR   16
#define NEDGE  (NNODES * KNBR)
#define NTILES (NEDGE / 128)          // 1250

// ---------------- scratch (static device globals; no allocation) ------------
__device__ __align__(16) unsigned char g_w2p[12 * 16384];   // W2 [chunk][hi/lo] fp16 SW128 tiles
__device__ __align__(16) uint32_t g_w1f[2048];              // W1 B-fragments [nt][term][lane][4]

// ---------------- helpers ----------------------------------------------------
__device__ __forceinline__ uint32_t sw128(uint32_t o) { return o ^ ((o >> 3) & 0x70u); }

__device__ __forceinline__ uint32_t smem_u32(const void* p) {
    uint32_t a;
    asm("{ .reg .u64 t; cvta.to.shared.u64 t, %1; cvt.u32.u64 %0, t; }" : "=r"(a) : "l"(p));
    return a;
}
__device__ __forceinline__ void ldsm_x4(uint32_t* r, uint32_t addr) {
    asm volatile("ldmatrix.sync.aligned.m8n8.x4.shared.b16 {%0,%1,%2,%3}, [%4];"
                 : "=r"(r[0]), "=r"(r[1]), "=r"(r[2]), "=r"(r[3]) : "r"(addr));
}
__device__ __forceinline__ void mma16816h(float* c, const uint32_t* a, const uint32_t* b) {
    asm volatile(
        "mma.sync.aligned.m16n8k16.row.col.f32.f16.f16.f32 "
        "{%0,%1,%2,%3}, {%4,%5,%6,%7}, {%8,%9}, {%0,%1,%2,%3};"
        : "+f"(c[0]), "+f"(c[1]), "+f"(c[2]), "+f"(c[3])
        : "r"(a[0]), "r"(a[1]), "r"(a[2]), "r"(a[3]), "r"(b[0]), "r"(b[1]));
}
__device__ __forceinline__ void cpa16(uint32_t dst, const void* src) {
    asm volatile("cp.async.cg.shared.global [%0], [%1], 16;" :: "r"(dst), "l"(src));
}
#define CPA_COMMIT() asm volatile("cp.async.commit_group;" ::: "memory")
#define CPA_WAIT0()  asm volatile("cp.async.wait_group 0;" ::: "memory")

__device__ __forceinline__ uint32_t packh2(float x, float y) {
    __half2 h = __floats2half2_rn(x, y);
    return *(uint32_t*)&h;
}
// fast gelu: A&S 7.1.25 erf, |abs err| <= 2.5e-5
__device__ __forceinline__ float gelu_fast(float v) {
    float x = fabsf(v) * 0.70710678118654752f;
    float w = fmaf(0.47047f, x, 1.0f);
    float t;
    asm("rcp.approx.f32 %0, %1;" : "=f"(t) : "f"(w));
    float P = t * fmaf(t, fmaf(t, 0.7478556f, -0.0958798f), 0.3480242f);
    float E = __expf(-x * x);
    float er = fmaf(-P, E, 1.0f);
    er = copysignf(er, v);
    return v * 0.5f * (1.0f + er);
}

// ---------------- kernel 0: W2 split/swizzle (128-row chunks) + W1 table -----
__global__ void k0_prep(const float* __restrict__ W2, const float* __restrict__ W1) {
    int idx = blockIdx.x * 256 + threadIdx.x;
    if (idx < 2048) {   // W1 B-fragments: idx = ((nt*2+term)*32+lane)*4 + comp
        int comp = idx & 3, lane = (idx >> 2) & 31, term = (idx >> 7) & 1, nt = idx >> 8;
        int n = nt * 8 + (lane >> 2);
        int s = comp >> 1, reg = comp & 1;
        int kb = s * 16 + (lane & 3) * 2 + reg * 8;
        float v0 = W1[n * 32 + kb], v1 = W1[n * 32 + kb + 1];
        if (term == 0) {
            g_w1f[idx] = packh2(v0, v1);
        } else {
            float r0 = v0 - __half2float(__float2half_rn(v0));
            float r1 = v1 - __half2float(__float2half_rn(v1));
            g_w1f[idx] = packh2(r0, r1);
        }
    }
    if (idx >= 768 * 64) return;
    int r = idx >> 6, c = idx & 63;
    int ch = r >> 7, n = r & 127;
    float x = W2[idx];
    __half hi = __float2half_rn(x);
    __half lo = __float2half_rn(x - __half2float(hi));
    uint32_t off = sw128((uint32_t)(n * 128 + c * 2));
    *(__half*)(g_w2p + (size_t)(ch * 2 + 0) * 16384 + off) = hi;
    *(__half*)(g_w2p + (size_t)(ch * 2 + 1) * 16384 + off) = lo;
}

// ---------------- kernel 2: fully fused edge pipeline -------------------------
#define S_TMP  0                    // 8192  (tmp 128x16 f32; outsm overlay later)
#define S_BL   8192                 // 3072
#define S_B0   11264                // 32768 (B buf0; sc_s/v_s overlay in epilogue)
#define S_B1   44032                // 32768 (B buf1)
#define S_OUT  76800                // 25088 (out 128x49)
#define S_TOT  101888

#define SV_SC  (S_B0)               // sc_s: 128*4 f32 = 2048
#define SV_V   (S_B0 + 2048)        // v_s: 128*32 f32 = 16384

__global__ void __launch_bounds__(256, 2)
k2_fused(const float* __restrict__ ef,
         const float* __restrict__ b1lin,
         const float* __restrict__ f,
         const int*   __restrict__ nidx,
         const float* __restrict__ b1,
         const float* __restrict__ b2,
         const float* __restrict__ b2l,
         const float* __restrict__ Wout,
         const float* __restrict__ bias,
         float* __restrict__ out) {
    extern __shared__ __align__(1024) unsigned char smem[];
    const uint32_t sb = smem_u32(smem);
    float* tmp_s = (float*)(smem + S_TMP);
    float* bl_s  = (float*)(smem + S_BL);
    float* out_s = (float*)(smem + S_OUT);

    const int tid = threadIdx.x, wid = tid >> 5, lane = tid & 31;
    const int e0 = blockIdx.x << 7;
    const int wn = wid >> 2, wm = wid & 3;

    // ---- async staging: bl (3KB) + B chunk0 (32KB) -------------------------
    if (tid < 192) cpa16(sb + S_BL + tid * 16, (const unsigned char*)b2l + tid * 16);
    for (int i = tid; i < 2048; i += 256) cpa16(sb + S_B0 + i * 16, g_w2p + i * 16);
    CPA_COMMIT();

    // ---- MLP via HMMA: ef fragments (A) straight from gmem, hi/lo split ----
    uint32_t aF[32];
    {
        uint32_t aefH[16], aefL[16];
        const int r0g = e0 + wm * 32 + (lane >> 2);
        const int kq = (lane & 3) * 2;
#pragma unroll
        for (int t = 0; t < 2; ++t)
#pragma unroll
            for (int s = 0; s < 2; ++s)
#pragma unroll
                for (int c = 0; c < 4; ++c) {
                    int rr = c & 1, ks = c >> 1;
                    int row = r0g + t * 16 + rr * 8;
                    int kk = s * 16 + ks * 8 + kq;
                    float2 v = *(const float2*)&ef[(size_t)row * 32 + kk];
                    float h0 = __half2float(__float2half_rn(v.x));
                    float h1 = __half2float(__float2half_rn(v.y));
                    aefH[t * 8 + s * 4 + c] = packh2(v.x, v.y);
                    aefL[t * 8 + s * 4 + c] = packh2(v.x - h0, v.y - h1);
                }

        // ---- h-GEMM: two independent 3-chains per (nt,t), then merge -------
#pragma unroll
        for (int nt = 0; nt < 8; ++nt) {
            uint4 wH = *(const uint4*)&g_w1f[(nt * 2 + 0) * 128 + lane * 4];
            uint4 wL = *(const uint4*)&g_w1f[(nt * 2 + 1) * 128 + lane * 4];
            uint32_t bh0[2] = {wH.x, wH.y}, bh1[2] = {wH.z, wH.w};
            uint32_t bl0[2] = {wL.x, wL.y}, bl1[2] = {wL.z, wL.w};
            float2 bl2 = *(const float2*)&b1lin[nt * 8 + (lane & 3) * 2];
#pragma unroll
            for (int t = 0; t < 2; ++t) {
                float ca[4] = {bl2.x, bl2.y, bl2.x, bl2.y};
                float cb[4] = {0.f, 0.f, 0.f, 0.f};
                mma16816h(ca, &aefH[t * 8 + 0], bh0);
                mma16816h(cb, &aefH[t * 8 + 4], bh1);
                mma16816h(ca, &aefL[t * 8 + 0], bh0);
                mma16816h(cb, &aefL[t * 8 + 4], bh1);
                mma16816h(ca, &aefH[t * 8 + 0], bl0);
                mma16816h(cb, &aefH[t * 8 + 4], bl1);
                float v0 = gelu_fast(ca[0] + cb[0]);
                float v1 = gelu_fast(ca[1] + cb[1]);
                float v2 = gelu_fast(ca[2] + cb[2]);
                float v3 = gelu_fast(ca[3] + cb[3]);
                int base = t * 16 + 4 * (nt >> 1) + (nt & 1) * 2;
                aF[base]     = packh2(v0, v1);
                aF[base + 1] = packh2(v2, v3);
            }
        }
    }

    // ---- tmp: lanes 0-15, 16 edges of this warp (bit-exact) ----------------
    {
        const int pbase = wid * 16;
        if (lane < 16) {
            int m = lane >> 1, l = lane & 1;
#pragma unroll 4
            for (int it = 0; it < 16; ++it) {
                int erow = pbase + it;
                int e = e0 + erow;
                int nbr = nidx[e];
                const float* frow = f + (size_t)nbr * 32 + m * 4;
                const float* brow = b1 + (size_t)e * 8;
                float t = 0.f;
#pragma unroll
                for (int d = 0; d < 4; ++d)
                    t = fmaf(frow[d], brow[d * 2 + l], t);
                tmp_s[erow * 16 + lane] = t;
            }
        }
    }
    CPA_WAIT0();       // B0 + bl arrived
    __syncthreads();   // tmp_s complete + cp.async visible to all

    const int er0 = wm * 32 + (lane >> 2);
    const int jq  = (lane & 3) * 2;
    const uint32_t rbase = (uint32_t)(wn * 64 + (lane & 7)) * 128 + ((lane >> 3) << 4);

    float acc0 = 0.f, acc1 = 0.f, acc2 = 0.f, acc3 = 0.f;

#pragma unroll 1
    for (int ch = 0; ch < 6; ++ch) {
        const uint32_t bufC = (ch & 1) ? (sb + S_B1) : (sb + S_B0);
        const uint32_t bufN = (ch & 1) ? (sb + S_B0) : (sb + S_B1);
        const unsigned char* srcN = g_w2p + (size_t)(ch + 1) * 32768;
        const bool pf = (ch < 5);

        // software-pipelined B fragments: bf[buf][0..7]=hi, [8..15]=lo
        uint32_t bf[2][16];
        {
            uint32_t rb = rbase;   // nt = 0
            ldsm_x4(&bf[0][0],  bufC + sw128(rb));
            ldsm_x4(&bf[0][4],  bufC + sw128(rb + 64));
            ldsm_x4(&bf[0][8],  bufC + 16384 + sw128(rb));
            ldsm_x4(&bf[0][12], bufC + 16384 + sw128(rb + 64));
        }

#pragma unroll
        for (int nt = 0; nt < 8; ++nt) {
            uint32_t* bC = bf[nt & 1];
            // issue nt+1's ldmatrix BEFORE nt's MMA block (latency hidden)
            if (nt < 7) {
                uint32_t* bN = bf[(nt + 1) & 1];
                uint32_t rb = rbase + (uint32_t)(nt + 1) * 8 * 128;
                ldsm_x4(&bN[0],  bufC + sw128(rb));
                ldsm_x4(&bN[4],  bufC + sw128(rb + 64));
                ldsm_x4(&bN[8],  bufC + 16384 + sw128(rb));
                ldsm_x4(&bN[12], bufC + 16384 + sw128(rb + 64));
            }
            // spread next-chunk prefetch over nt=0..3
            if (pf && nt < 4) {
                int i0 = tid + 256 * (2 * nt);
                int i1 = tid + 256 * (2 * nt + 1);
                cpa16(bufN + i0 * 16, srcN + i0 * 16);
                cpa16(bufN + i1 * 16, srcN + i1 * 16);
                if (nt == 3) CPA_COMMIT();
            }

            const int nb = wn * 64 + nt * 8;
            const int g0 = ch * 128 + nb + jq;
            float2 blv = *(float2*)&bl_s[g0];
            float c0[4] = {blv.x, blv.y, blv.x, blv.y};
            float c1[4] = {blv.x, blv.y, blv.x, blv.y};
#pragma unroll
            for (int s = 0; s < 4; ++s) {
                mma16816h(c0, &aF[4 * s],      &bC[2 * s]);
                mma16816h(c0, &aF[4 * s],      &bC[8 + 2 * s]);
                mma16816h(c1, &aF[16 + 4 * s], &bC[2 * s]);
                mma16816h(c1, &aF[16 + 4 * s], &bC[8 + 2 * s]);
            }

            // tmp from smem (values identical; tv registers traded for pipeline)
            const int j0 = ((nt & 1) << 3) + jq;
            float2 t0 = *(float2*)&tmp_s[er0 * 16 + j0];
            float2 t1 = *(float2*)&tmp_s[(er0 + 8) * 16 + j0];
            float2 t2 = *(float2*)&tmp_s[(er0 + 16) * 16 + j0];
            float2 t3 = *(float2*)&tmp_s[(er0 + 24) * 16 + j0];
            acc0 += c0[0] * t0.x + c0[1] * t0.y;
            acc1 += c0[2] * t1.x + c0[3] * t1.y;
            acc2 += c1[0] * t2.x + c1[1] * t2.y;
            acc3 += c1[2] * t3.x + c1[3] * t3.y;

            if (nt & 1) {
                acc0 += __shfl_xor_sync(0xffffffffu, acc0, 1);
                acc0 += __shfl_xor_sync(0xffffffffu, acc0, 2);
                acc1 += __shfl_xor_sync(0xffffffffu, acc1, 1);
                acc1 += __shfl_xor_sync(0xffffffffu, acc1, 2);
                acc2 += __shfl_xor_sync(0xffffffffu, acc2, 1);
                acc2 += __shfl_xor_sync(0xffffffffu, acc2, 2);
                acc3 += __shfl_xor_sync(0xffffffffu, acc3, 1);
                acc3 += __shfl_xor_sync(0xffffffffu, acc3, 2);
                if ((lane & 3) == 0) {
                    int i = ch * 8 + wn * 4 + (nt >> 1);
                    out_s[er0 * 49 + i]        = acc0;
                    out_s[(er0 + 8) * 49 + i]  = acc1;
                    out_s[(er0 + 16) * 49 + i] = acc2;
                    out_s[(er0 + 24) * 49 + i] = acc3;
                }
                acc0 = 0.f; acc1 = 0.f; acc2 = 0.f; acc3 = 0.f;
            }
        }

        if (pf) {
            CPA_WAIT0();
            __syncthreads();
        }
    }
    __syncthreads();   // out_s complete; B buffers dead -> sc_s/v_s overlay

    // ---- per-edge: qkv = out48.reshape(24,2) @ b2f -> scores + v (to smem) ----
    float* sc_s = (float*)(smem + SV_SC);
    float* v_s  = (float*)(smem + SV_V);
    if (tid < 128) {
        int e = e0 + tid;
        const float* o48 = out_s + tid * 49;
        float bb[8];
#pragma unroll
        for (int x = 0; x < 8; ++x) bb[x] = b2[(size_t)e * 8 + x];

#pragma unroll
        for (int h = 0; h < 4; ++h) {
            float s = 0.f;
#pragma unroll
            for (int mm = 0; mm < 2; ++mm) {
                int m = 2 * h + mm;
#pragma unroll
                for (int d = 0; d < 4; ++d) {
                    float q = o48[m * 2]       * bb[d] + o48[m * 2 + 1]       * bb[4 + d];
                    float k = o48[(8 + m) * 2] * bb[d] + o48[(8 + m) * 2 + 1] * bb[4 + d];
                    s = fmaf(q, k, s);
                }
            }
            sc_s[tid * 4 + h] = s * 0.35355339059327376f;
        }
#pragma unroll
        for (int m = 0; m < 8; ++m)
#pragma unroll
            for (int d = 0; d < 4; ++d)
                v_s[tid * 32 + m * 4 + d] =
                    o48[(16 + m) * 2] * bb[d] + o48[(16 + m) * 2 + 1] * bb[4 + d];
    }
    __syncthreads();

    // ---- per-node attention: warp wid handles node blockIdx.x*8 + wid ----
    {
        float* outsm = (float*)(smem + S_TMP) + wid * 33;   // overlay on tmp_s
        int n = blockIdx.x * 8 + wid;
        int nb = wid * 16;

        float2 sc2 = *(float2*)&sc_s[nb * 4 + lane * 2];
        float s0 = sc2.x, s1 = sc2.y;

        float m0 = s0, m1 = s1;
#pragma unroll
        for (int off = 2; off < 32; off <<= 1) {
            m0 = fmaxf(m0, __shfl_xor_sync(0xffffffffu, m0, off));
            m1 = fmaxf(m1, __shfl_xor_sync(0xffffffffu, m1, off));
        }
        float e0v = expf(s0 - m0), e1v = expf(s1 - m1);
        float z0 = e0v, z1 = e1v;
#pragma unroll
        for (int off = 2; off < 32; off <<= 1) {
            z0 += __shfl_xor_sync(0xffffffffu, z0, off);
            z1 += __shfl_xor_sync(0xffffffffu, z1, off);
        }
        float a0 = e0v / z0, a1 = e1v / z1;

        const int m_mine = lane & 7;
        const int hsel   = (m_mine >> 1) & 1;
        float r[4] = {0.f, 0.f, 0.f, 0.f};
#pragma unroll
        for (int it = 0; it < 4; ++it) {
            float4 vv = *(float4*)&v_s[nb * 32 + it * 128 + lane * 4];
            int lsrc = 8 * it + ((lane >> 3) << 1) + ((lane >> 2) & 1);
            float av0 = __shfl_sync(0xffffffffu, a0, lsrc);
            float av1 = __shfl_sync(0xffffffffu, a1, lsrc);
            float a = hsel ? av1 : av0;
            r[0] = fmaf(a, vv.x, r[0]);
            r[1] = fmaf(a, vv.y, r[1]);
            r[2] = fmaf(a, vv.z, r[2]);
            r[3] = fmaf(a, vv.w, r[3]);
        }
#pragma unroll
        for (int off = 8; off < 32; off <<= 1)
#pragma unroll
            for (int d = 0; d < 4; ++d)
                r[d] += __shfl_xor_sync(0xffffffffu, r[d], off);

        if (lane < 8) {
#pragma unroll
            for (int d = 0; d < 4; ++d)
                outsm[m_mine * 4 + d] = r[d];
        }
        __syncwarp();

        int mm = lane >> 2, dd = lane & 3;
        int o = (dd == 0) ? mm : 8 + mm;
        float val = (dd == 0) ? bias[mm] : 0.f;
#pragma unroll
        for (int mp = 0; mp < 8; ++mp)
            val = fmaf(Wout[o * 8 + mp], outsm[mp * 4 + dd], val);
        out[(size_t)n * 32 + lane] = val;
    }
}

// ---------------- launcher ----------------------------------------------------
extern "C" void kernel_launch(void* const* d_in, const int* in_sizes, int n_in,
                              void* d_out, int out_size) {
    const float* b1   = (const float*)d_in[0];
    const float* b2   = (const float*)d_in[1];
    const float* ef   = (const float*)d_in[2];
    const float* f    = (const float*)d_in[3];
    const int*   nidx = (const int*)  d_in[4];
    const float* W1   = (const float*)d_in[5];
    const float* b1l  = (const float*)d_in[6];
    const float* W2   = (const float*)d_in[7];
    const float* b2l  = (const float*)d_in[8];
    const float* Wout = (const float*)d_in[9];
    const float* bias = (const float*)d_in[10];
    float* out = (float*)d_out;
    (void)in_sizes; (void)n_in; (void)out_size;

    cudaFuncSetAttribute(k2_fused, cudaFuncAttributeMaxDynamicSharedMemorySize, S_TOT);

    k0_prep<<<(768 * 64 + 255) / 256, 256>>>(W2, W1);
    k2_fused<<<NTILES, 256, S_TOT>>>(ef, b1l, f, nidx, b1, b2, b2l, Wout, bias, out);
}

// round 16
// speedup vs baseline: 1.0793x; 1.0793x over previous
#include <cuda_runtime.h>
#include <cuda_fp16.h>
#include <math.h>
#include <stdint.h>

#define NNODES 10000
#define KNBR   16
#define NEDGE  (NNODES * KNBR)
#define NTILES (NEDGE / 128)          // 1250

// ---------------- scratch (static device globals; no allocation) ------------
__device__ __align__(16) unsigned char g_w2p[12 * 16384];   // W2 [chunk][hi/lo] fp16 SW128 tiles
__device__ __align__(16) uint32_t g_w1f[2048];              // W1 B-fragments [nt][term][lane][4]

// ---------------- helpers ----------------------------------------------------
__device__ __forceinline__ uint32_t sw128(uint32_t o) { return o ^ ((o >> 3) & 0x70u); }

__device__ __forceinline__ uint32_t smem_u32(const void* p) {
    uint32_t a;
    asm("{ .reg .u64 t; cvta.to.shared.u64 t, %1; cvt.u32.u64 %0, t; }" : "=r"(a) : "l"(p));
    return a;
}
__device__ __forceinline__ void ldsm_x4(uint32_t* r, uint32_t addr) {
    asm volatile("ldmatrix.sync.aligned.m8n8.x4.shared.b16 {%0,%1,%2,%3}, [%4];"
                 : "=r"(r[0]), "=r"(r[1]), "=r"(r[2]), "=r"(r[3]) : "r"(addr));
}
__device__ __forceinline__ void mma16816h(float* c, const uint32_t* a, const uint32_t* b) {
    asm volatile(
        "mma.sync.aligned.m16n8k16.row.col.f32.f16.f16.f32 "
        "{%0,%1,%2,%3}, {%4,%5,%6,%7}, {%8,%9}, {%0,%1,%2,%3};"
        : "+f"(c[0]), "+f"(c[1]), "+f"(c[2]), "+f"(c[3])
        : "r"(a[0]), "r"(a[1]), "r"(a[2]), "r"(a[3]), "r"(b[0]), "r"(b[1]));
}
__device__ __forceinline__ void cpa16(uint32_t dst, const void* src) {
    asm volatile("cp.async.cg.shared.global [%0], [%1], 16;" :: "r"(dst), "l"(src));
}
#define CPA_COMMIT() asm volatile("cp.async.commit_group;" ::: "memory")
#define CPA_WAIT0()  asm volatile("cp.async.wait_group 0;" ::: "memory")

__device__ __forceinline__ uint32_t packh2(float x, float y) {
    __half2 h = __floats2half2_rn(x, y);
    return *(uint32_t*)&h;
}
// fast gelu: A&S 7.1.25 erf, |abs err| <= 2.5e-5
__device__ __forceinline__ float gelu_fast(float v) {
    float x = fabsf(v) * 0.70710678118654752f;
    float w = fmaf(0.47047f, x, 1.0f);
    float t;
    asm("rcp.approx.f32 %0, %1;" : "=f"(t) : "f"(w));
    float P = t * fmaf(t, fmaf(t, 0.7478556f, -0.0958798f), 0.3480242f);
    float E = __expf(-x * x);
    float er = fmaf(-P, E, 1.0f);
    er = copysignf(er, v);
    return v * 0.5f * (1.0f + er);
}

// ---------------- kernel 0: W2 split/swizzle (128-row chunks) + W1 table -----
__global__ void k0_prep(const float* __restrict__ W2, const float* __restrict__ W1) {
    int idx = blockIdx.x * 256 + threadIdx.x;
    if (idx < 2048) {   // W1 B-fragments: idx = ((nt*2+term)*32+lane)*4 + comp
        int comp = idx & 3, lane = (idx >> 2) & 31, term = (idx >> 7) & 1, nt = idx >> 8;
        int n = nt * 8 + (lane >> 2);
        int s = comp >> 1, reg = comp & 1;
        int kb = s * 16 + (lane & 3) * 2 + reg * 8;
        float v0 = W1[n * 32 + kb], v1 = W1[n * 32 + kb + 1];
        if (term == 0) {
            g_w1f[idx] = packh2(v0, v1);
        } else {
            float r0 = v0 - __half2float(__float2half_rn(v0));
            float r1 = v1 - __half2float(__float2half_rn(v1));
            g_w1f[idx] = packh2(r0, r1);
        }
    }
    if (idx >= 768 * 64) return;
    int r = idx >> 6, c = idx & 63;
    int ch = r >> 7, n = r & 127;
    float x = W2[idx];
    __half hi = __float2half_rn(x);
    __half lo = __float2half_rn(x - __half2float(hi));
    uint32_t off = sw128((uint32_t)(n * 128 + c * 2));
    *(__half*)(g_w2p + (size_t)(ch * 2 + 0) * 16384 + off) = hi;
    *(__half*)(g_w2p + (size_t)(ch * 2 + 1) * 16384 + off) = lo;
}

// ---------------- kernel 2: fully fused edge pipeline -------------------------
#define S_TMP  0                    // 8192  (tmp 128x16 f32; outsm overlay later)
#define S_BL   8192                 // 3072
#define S_B0   11264                // 32768 (B buf0; sc_s/v_s overlay in epilogue)
#define S_B1   44032                // 32768 (B buf1)
#define S_OUT  76800                // 25088 (out 128x49)
#define S_TOT  101888

#define SV_SC  (S_B0)               // sc_s: 128*4 f32 = 2048
#define SV_V   (S_B0 + 2048)        // v_s: 128*32 f32 = 16384

__global__ void __launch_bounds__(256, 2)
k2_fused(const float* __restrict__ ef,
         const float* __restrict__ b1lin,
         const float* __restrict__ f,
         const int*   __restrict__ nidx,
         const float* __restrict__ b1,
         const float* __restrict__ b2,
         const float* __restrict__ b2l,
         const float* __restrict__ Wout,
         const float* __restrict__ bias,
         float* __restrict__ out) {
    extern __shared__ __align__(1024) unsigned char smem[];
    const uint32_t sb = smem_u32(smem);
    float* tmp_s = (float*)(smem + S_TMP);
    float* bl_s  = (float*)(smem + S_BL);
    float* out_s = (float*)(smem + S_OUT);

    const int tid = threadIdx.x, wid = tid >> 5, lane = tid & 31;
    const int e0 = blockIdx.x << 7;
    const int wn = wid >> 2, wm = wid & 3;

    // ---- async staging: bl (3KB) + B chunk0 (32KB) -------------------------
    if (tid < 192) cpa16(sb + S_BL + tid * 16, (const unsigned char*)b2l + tid * 16);
    for (int i = tid; i < 2048; i += 256) cpa16(sb + S_B0 + i * 16, g_w2p + i * 16);
    CPA_COMMIT();

    // ---- MLP via HMMA: ef fragments (A) straight from gmem, hi/lo split ----
    uint32_t aF[32];
    {
        uint32_t aefH[16], aefL[16];
        const int r0g = e0 + wm * 32 + (lane >> 2);
        const int kq = (lane & 3) * 2;
#pragma unroll
        for (int t = 0; t < 2; ++t)
#pragma unroll
            for (int s = 0; s < 2; ++s)
#pragma unroll
                for (int c = 0; c < 4; ++c) {
                    int rr = c & 1, ks = c >> 1;
                    int row = r0g + t * 16 + rr * 8;
                    int kk = s * 16 + ks * 8 + kq;
                    float2 v = *(const float2*)&ef[(size_t)row * 32 + kk];
                    float h0 = __half2float(__float2half_rn(v.x));
                    float h1 = __half2float(__float2half_rn(v.y));
                    aefH[t * 8 + s * 4 + c] = packh2(v.x, v.y);
                    aefL[t * 8 + s * 4 + c] = packh2(v.x - h0, v.y - h1);
                }

        // ---- h-GEMM: two independent 3-chains per (nt,t), then merge -------
#pragma unroll
        for (int nt = 0; nt < 8; ++nt) {
            uint4 wH = *(const uint4*)&g_w1f[(nt * 2 + 0) * 128 + lane * 4];
            uint4 wL = *(const uint4*)&g_w1f[(nt * 2 + 1) * 128 + lane * 4];
            uint32_t bh0[2] = {wH.x, wH.y}, bh1[2] = {wH.z, wH.w};
            uint32_t bl0[2] = {wL.x, wL.y}, bl1[2] = {wL.z, wL.w};
            float2 bl2 = *(const float2*)&b1lin[nt * 8 + (lane & 3) * 2];
#pragma unroll
            for (int t = 0; t < 2; ++t) {
                float ca[4] = {bl2.x, bl2.y, bl2.x, bl2.y};
                float cb[4] = {0.f, 0.f, 0.f, 0.f};
                mma16816h(ca, &aefH[t * 8 + 0], bh0);
                mma16816h(cb, &aefH[t * 8 + 4], bh1);
                mma16816h(ca, &aefL[t * 8 + 0], bh0);
                mma16816h(cb, &aefL[t * 8 + 4], bh1);
                mma16816h(ca, &aefH[t * 8 + 0], bl0);
                mma16816h(cb, &aefH[t * 8 + 4], bl1);
                float v0 = gelu_fast(ca[0] + cb[0]);
                float v1 = gelu_fast(ca[1] + cb[1]);
                float v2 = gelu_fast(ca[2] + cb[2]);
                float v3 = gelu_fast(ca[3] + cb[3]);
                int base = t * 16 + 4 * (nt >> 1) + (nt & 1) * 2;
                aF[base]     = packh2(v0, v1);
                aF[base + 1] = packh2(v2, v3);
            }
        }
    }

    // ---- tmp: lanes 0-15, 16 edges of this warp (bit-exact) ----------------
    {
        const int pbase = wid * 16;
        if (lane < 16) {
            int m = lane >> 1, l = lane & 1;
#pragma unroll 4
            for (int it = 0; it < 16; ++it) {
                int erow = pbase + it;
                int e = e0 + erow;
                int nbr = nidx[e];
                const float* frow = f + (size_t)nbr * 32 + m * 4;
                const float* brow = b1 + (size_t)e * 8;
                float t = 0.f;
#pragma unroll
                for (int d = 0; d < 4; ++d)
                    t = fmaf(frow[d], brow[d * 2 + l], t);
                tmp_s[erow * 16 + lane] = t;
            }
        }
    }
    CPA_WAIT0();       // B0 + bl arrived
    __syncthreads();   // tmp_s complete + cp.async visible to all

    const int er0 = wm * 32 + (lane >> 2);
    const int jq  = (lane & 3) * 2;

    // hoist tmp values (invariant across chunks)
    float tv[16];
#pragma unroll
    for (int rr = 0; rr < 4; ++rr) {
        float2 ta = *(float2*)&tmp_s[(er0 + rr * 8) * 16 + jq];
        float2 tb = *(float2*)&tmp_s[(er0 + rr * 8) * 16 + 8 + jq];
        tv[rr * 4 + 0] = ta.x; tv[rr * 4 + 1] = ta.y;
        tv[rr * 4 + 2] = tb.x; tv[rr * 4 + 3] = tb.y;
    }

    float acc0 = 0.f, acc1 = 0.f, acc2 = 0.f, acc3 = 0.f;

#pragma unroll 1
    for (int ch = 0; ch < 6; ++ch) {
        const uint32_t bufC = (ch & 1) ? (sb + S_B1) : (sb + S_B0);
        const uint32_t bufN = (ch & 1) ? (sb + S_B0) : (sb + S_B1);
        const unsigned char* srcN = g_w2p + (size_t)(ch + 1) * 32768;
        const bool pf = (ch < 5);

#pragma unroll
        for (int nt = 0; nt < 8; ++nt) {
            // spread next-chunk prefetch over all 8 nt (1 cp.async per thread)
            if (pf) {
                int i0 = tid + 256 * nt;
                cpa16(bufN + i0 * 16, srcN + i0 * 16);
                if (nt == 7) CPA_COMMIT();
            }

            const int nb = wn * 64 + nt * 8;    // col base within chunk
            uint32_t bH[8], bL[8];
            uint32_t rb = (uint32_t)(nb + (lane & 7)) * 128 + ((lane >> 3) << 4);
#pragma unroll
            for (int p = 0; p < 2; ++p) {
                uint32_t off = sw128(rb + 64 * p);
                ldsm_x4(&bH[4 * p], bufC + off);
                ldsm_x4(&bL[4 * p], bufC + 16384 + off);
            }

            // 2 chains (m-tile 0/1); hi+lo accumulate into same acc; bl in init
            const int g0 = ch * 128 + nb + jq;
            float2 blv = *(float2*)&bl_s[g0];
            float c0[4] = {blv.x, blv.y, blv.x, blv.y};
            float c1[4] = {blv.x, blv.y, blv.x, blv.y};
#pragma unroll
            for (int s = 0; s < 4; ++s) {
                mma16816h(c0, &aF[4 * s],      &bH[2 * s]);
                mma16816h(c0, &aF[4 * s],      &bL[2 * s]);
                mma16816h(c1, &aF[16 + 4 * s], &bH[2 * s]);
                mma16816h(c1, &aF[16 + 4 * s], &bL[2 * s]);
            }

            const int sel = (nt & 1) << 1;
            acc0 += c0[0] * tv[sel]      + c0[1] * tv[sel + 1];
            acc1 += c0[2] * tv[4 + sel]  + c0[3] * tv[4 + sel + 1];
            acc2 += c1[0] * tv[8 + sel]  + c1[1] * tv[8 + sel + 1];
            acc3 += c1[2] * tv[12 + sel] + c1[3] * tv[12 + sel + 1];

            if (nt & 1) {
                acc0 += __shfl_xor_sync(0xffffffffu, acc0, 1);
                acc0 += __shfl_xor_sync(0xffffffffu, acc0, 2);
                acc1 += __shfl_xor_sync(0xffffffffu, acc1, 1);
                acc1 += __shfl_xor_sync(0xffffffffu, acc1, 2);
                acc2 += __shfl_xor_sync(0xffffffffu, acc2, 1);
                acc2 += __shfl_xor_sync(0xffffffffu, acc2, 2);
                acc3 += __shfl_xor_sync(0xffffffffu, acc3, 1);
                acc3 += __shfl_xor_sync(0xffffffffu, acc3, 2);
                if ((lane & 3) == 0) {
                    int i = ch * 8 + wn * 4 + (nt >> 1);
                    out_s[er0 * 49 + i]        = acc0;
                    out_s[(er0 + 8) * 49 + i]  = acc1;
                    out_s[(er0 + 16) * 49 + i] = acc2;
                    out_s[(er0 + 24) * 49 + i] = acc3;
                }
                acc0 = 0.f; acc1 = 0.f; acc2 = 0.f; acc3 = 0.f;
            }
        }

        if (pf) {
            CPA_WAIT0();
            __syncthreads();
        }
    }
    __syncthreads();   // out_s complete; B buffers dead -> sc_s/v_s overlay

    // ---- per-edge: qkv -> scores + v; 2 threads per edge (256 threads) -----
    float* sc_s = (float*)(smem + SV_SC);
    float* v_s  = (float*)(smem + SV_V);
    {
        int eloc = tid >> 1;           // edge 0..127
        int half = tid & 1;            // heads half*2..half*2+1, v-rows half*4..+3
        int e = e0 + eloc;
        const float* o48 = out_s + eloc * 49;
        float bb[8];
#pragma unroll
        for (int x = 0; x < 8; ++x) bb[x] = b2[(size_t)e * 8 + x];

#pragma unroll
        for (int hh = 0; hh < 2; ++hh) {
            int h = half * 2 + hh;
            float s = 0.f;
#pragma unroll
            for (int mm = 0; mm < 2; ++mm) {
                int m = 2 * h + mm;
#pragma unroll
                for (int d = 0; d < 4; ++d) {
                    float q = o48[m * 2]       * bb[d] + o48[m * 2 + 1]       * bb[4 + d];
                    float k = o48[(8 + m) * 2] * bb[d] + o48[(8 + m) * 2 + 1] * bb[4 + d];
                    s = fmaf(q, k, s);
                }
            }
            sc_s[eloc * 4 + h] = s * 0.35355339059327376f;
        }
#pragma unroll
        for (int mm = 0; mm < 4; ++mm) {
            int m = half * 4 + mm;
#pragma unroll
            for (int d = 0; d < 4; ++d)
                v_s[eloc * 32 + m * 4 + d] =
                    o48[(16 + m) * 2] * bb[d] + o48[(16 + m) * 2 + 1] * bb[4 + d];
        }
    }
    __syncthreads();

    // ---- per-node attention: warp wid handles node blockIdx.x*8 + wid ----
    {
        float* outsm = (float*)(smem + S_TMP) + wid * 33;   // overlay on tmp_s
        int n = blockIdx.x * 8 + wid;
        int nb = wid * 16;

        float2 sc2 = *(float2*)&sc_s[nb * 4 + lane * 2];
        float s0 = sc2.x, s1 = sc2.y;

        float m0 = s0, m1 = s1;
#pragma unroll
        for (int off = 2; off < 32; off <<= 1) {
            m0 = fmaxf(m0, __shfl_xor_sync(0xffffffffu, m0, off));
            m1 = fmaxf(m1, __shfl_xor_sync(0xffffffffu, m1, off));
        }
        float e0v = expf(s0 - m0), e1v = expf(s1 - m1);
        float z0 = e0v, z1 = e1v;
#pragma unroll
        for (int off = 2; off < 32; off <<= 1) {
            z0 += __shfl_xor_sync(0xffffffffu, z0, off);
            z1 += __shfl_xor_sync(0xffffffffu, z1, off);
        }
        float a0 = e0v / z0, a1 = e1v / z1;

        const int m_mine = lane & 7;
        const int hsel   = (m_mine >> 1) & 1;
        float r[4] = {0.f, 0.f, 0.f, 0.f};
#pragma unroll
        for (int it = 0; it < 4; ++it) {
            float4 vv = *(float4*)&v_s[nb * 32 + it * 128 + lane * 4];
            int lsrc = 8 * it + ((lane >> 3) << 1) + ((lane >> 2) & 1);
            float av0 = __shfl_sync(0xffffffffu, a0, lsrc);
            float av1 = __shfl_sync(0xffffffffu, a1, lsrc);
            float a = hsel ? av1 : av0;
            r[0] = fmaf(a, vv.x, r[0]);
            r[1] = fmaf(a, vv.y, r[1]);
            r[2] = fmaf(a, vv.z, r[2]);
            r[3] = fmaf(a, vv.w, r[3]);
        }
#pragma unroll
        for (int off = 8; off < 32; off <<= 1)
#pragma unroll
            for (int d = 0; d < 4; ++d)
                r[d] += __shfl_xor_sync(0xffffffffu, r[d], off);

        if (lane < 8) {
#pragma unroll
            for (int d = 0; d < 4; ++d)
                outsm[m_mine * 4 + d] = r[d];
        }
        __syncwarp();

        int mm = lane >> 2, dd = lane & 3;
        int o = (dd == 0) ? mm : 8 + mm;
        float val = (dd == 0) ? bias[mm] : 0.f;
#pragma unroll
        for (int mp = 0; mp < 8; ++mp)
            val = fmaf(Wout[o * 8 + mp], outsm[mp * 4 + dd], val);
        out[(size_t)n * 32 + lane] = val;
    }
}

// ---------------- launcher ----------------------------------------------------
extern "C" void kernel_launch(void* const* d_in, const int* in_sizes, int n_in,
                              void* d_out, int out_size) {
    const float* b1   = (const float*)d_in[0];
    const float* b2   = (const float*)d_in[1];
    const float* ef   = (const float*)d_in[2];
    const float* f    = (const float*)d_in[3];
    const int*   nidx = (const int*)  d_in[4];
    const float* W1   = (const float*)d_in[5];
    const float* b1l  = (const float*)d_in[6];
    const float* W2   = (const float*)d_in[7];
    const float* b2l  = (const float*)d_in[8];
    const float* Wout = (const float*)d_in[9];
    const float* bias = (const float*)d_in[10];
    float* out = (float*)d_out;
    (void)in_sizes; (void)n_in; (void)out_size;

    cudaFuncSetAttribute(k2_fused, cudaFuncAttributeMaxDynamicSharedMemorySize, S_TOT);

    k0_prep<<<(768 * 64 + 255) / 256, 256>>>(W2, W1);
    k2_fused<<<NTILES, 256, S_TOT>>>(ef, b1l, f, nidx, b1, b2, b2l, Wout, bias, out);
}

// round 17
// speedup vs baseline: 1.0926x; 1.0124x over previous
#include <cuda_runtime.h>
#include <cuda_fp16.h>
#include <math.h>
#include <stdint.h>

#define NNODES 10000
#define KNBR   16
#define NEDGE  (NNODES * KNBR)
#define NTILES (NEDGE / 128)          // 1250

// ---------------- scratch (static device globals; no allocation) ------------
__device__ __align__(16) unsigned char g_w2p[12 * 16384];   // W2 [chunk][hi/lo] fp16 SW128 tiles
__device__ __align__(16) uint32_t g_w1f[2048];              // W1 B-fragments [nt][term][lane][4]

// ---------------- helpers ----------------------------------------------------
__device__ __forceinline__ uint32_t sw128(uint32_t o) { return o ^ ((o >> 3) & 0x70u); }

__device__ __forceinline__ uint32_t smem_u32(const void* p) {
    uint32_t a;
    asm("{ .reg .u64 t; cvta.to.shared.u64 t, %1; cvt.u32.u64 %0, t; }" : "=r"(a) : "l"(p));
    return a;
}
__device__ __forceinline__ void ldsm_x4(uint32_t* r, uint32_t addr) {
    asm volatile("ldmatrix.sync.aligned.m8n8.x4.shared.b16 {%0,%1,%2,%3}, [%4];"
                 : "=r"(r[0]), "=r"(r[1]), "=r"(r[2]), "=r"(r[3]) : "r"(addr));
}
__device__ __forceinline__ void mma16816h(float* c, const uint32_t* a, const uint32_t* b) {
    asm volatile(
        "mma.sync.aligned.m16n8k16.row.col.f32.f16.f16.f32 "
        "{%0,%1,%2,%3}, {%4,%5,%6,%7}, {%8,%9}, {%0,%1,%2,%3};"
        : "+f"(c[0]), "+f"(c[1]), "+f"(c[2]), "+f"(c[3])
        : "r"(a[0]), "r"(a[1]), "r"(a[2]), "r"(a[3]), "r"(b[0]), "r"(b[1]));
}
__device__ __forceinline__ void cpa16(uint32_t dst, const void* src) {
    asm volatile("cp.async.cg.shared.global [%0], [%1], 16;" :: "r"(dst), "l"(src));
}
#define CPA_COMMIT() asm volatile("cp.async.commit_group;" ::: "memory")
#define CPA_WAIT0()  asm volatile("cp.async.wait_group 0;" ::: "memory")

__device__ __forceinline__ uint32_t packh2(float x, float y) {
    __half2 h = __floats2half2_rn(x, y);
    return *(uint32_t*)&h;
}
// fast gelu: A&S 7.1.25 erf, |abs err| <= 2.5e-5
__device__ __forceinline__ float gelu_fast(float v) {
    float x = fabsf(v) * 0.70710678118654752f;
    float w = fmaf(0.47047f, x, 1.0f);
    float t;
    asm("rcp.approx.f32 %0, %1;" : "=f"(t) : "f"(w));
    float P = t * fmaf(t, fmaf(t, 0.7478556f, -0.0958798f), 0.3480242f);
    float E = __expf(-x * x);
    float er = fmaf(-P, E, 1.0f);
    er = copysignf(er, v);
    return v * 0.5f * (1.0f + er);
}

// ---------------- kernel 0: W2 split/swizzle (128-row chunks) + W1 table -----
__global__ void k0_prep(const float* __restrict__ W2, const float* __restrict__ W1) {
    int idx = blockIdx.x * 256 + threadIdx.x;
    if (idx < 2048) {   // W1 B-fragments: idx = ((nt*2+term)*32+lane)*4 + comp
        int comp = idx & 3, lane = (idx >> 2) & 31, term = (idx >> 7) & 1, nt = idx >> 8;
        int n = nt * 8 + (lane >> 2);
        int s = comp >> 1, reg = comp & 1;
        int kb = s * 16 + (lane & 3) * 2 + reg * 8;
        float v0 = W1[n * 32 + kb], v1 = W1[n * 32 + kb + 1];
        if (term == 0) {
            g_w1f[idx] = packh2(v0, v1);
        } else {
            float r0 = v0 - __half2float(__float2half_rn(v0));
            float r1 = v1 - __half2float(__float2half_rn(v1));
            g_w1f[idx] = packh2(r0, r1);
        }
    }
    if (idx >= 768 * 64) return;
    int r = idx >> 6, c = idx & 63;
    int ch = r >> 7, n = r & 127;
    float x = W2[idx];
    __half hi = __float2half_rn(x);
    __half lo = __float2half_rn(x - __half2float(hi));
    uint32_t off = sw128((uint32_t)(n * 128 + c * 2));
    *(__half*)(g_w2p + (size_t)(ch * 2 + 0) * 16384 + off) = hi;
    *(__half*)(g_w2p + (size_t)(ch * 2 + 1) * 16384 + off) = lo;
}

// ---------------- kernel 2: fully fused edge pipeline -------------------------
#define S_TMP  0                    // 8192  (tmp 128x16 f32; outsm overlay later)
#define S_BL   8192                 // 3072
#define S_B0   11264                // 32768 (B buf0; sc_s/v_s overlay in epilogue)
#define S_B1   44032                // 32768 (B buf1)
#define S_OUT  76800                // 25088 (out 128x49)
#define S_TOT  101888

#define SV_SC  (S_B0)               // sc_s: 128*4 f32 = 2048
#define SV_V   (S_B0 + 2048)        // v_s: 128*32 f32 = 16384

__global__ void __launch_bounds__(256, 2)
k2_fused(const float* __restrict__ ef,
         const float* __restrict__ b1lin,
         const float* __restrict__ f,
         const int*   __restrict__ nidx,
         const float* __restrict__ b1,
         const float* __restrict__ b2,
         const float* __restrict__ b2l,
         const float* __restrict__ Wout,
         const float* __restrict__ bias,
         float* __restrict__ out) {
    extern __shared__ __align__(1024) unsigned char smem[];
    const uint32_t sb = smem_u32(smem);
    float* tmp_s = (float*)(smem + S_TMP);
    float* bl_s  = (float*)(smem + S_BL);
    float* out_s = (float*)(smem + S_OUT);

    const int tid = threadIdx.x, wid = tid >> 5, lane = tid & 31;
    const int e0 = blockIdx.x << 7;
    const int wn = wid >> 2, wm = wid & 3;

    // ---- async staging: bl (3KB) + B chunk0 (32KB) -------------------------
    if (tid < 192) cpa16(sb + S_BL + tid * 16, (const unsigned char*)b2l + tid * 16);
    for (int i = tid; i < 2048; i += 256) cpa16(sb + S_B0 + i * 16, g_w2p + i * 16);
    CPA_COMMIT();

    // ---- MLP via HMMA: ef fragments (A) straight from gmem, hi/lo split ----
    uint32_t aF[32];
    {
        uint32_t aefH[16], aefL[16];
        const int r0g = e0 + wm * 32 + (lane >> 2);
        const int kq = (lane & 3) * 2;
#pragma unroll
        for (int t = 0; t < 2; ++t)
#pragma unroll
            for (int s = 0; s < 2; ++s)
#pragma unroll
                for (int c = 0; c < 4; ++c) {
                    int rr = c & 1, ks = c >> 1;
                    int row = r0g + t * 16 + rr * 8;
                    int kk = s * 16 + ks * 8 + kq;
                    float2 v = *(const float2*)&ef[(size_t)row * 32 + kk];
                    float h0 = __half2float(__float2half_rn(v.x));
                    float h1 = __half2float(__float2half_rn(v.y));
                    aefH[t * 8 + s * 4 + c] = packh2(v.x, v.y);
                    aefL[t * 8 + s * 4 + c] = packh2(v.x - h0, v.y - h1);
                }

        // ---- h-GEMM: two independent 3-chains per (nt,t), then merge -------
#pragma unroll
        for (int nt = 0; nt < 8; ++nt) {
            uint4 wH = *(const uint4*)&g_w1f[(nt * 2 + 0) * 128 + lane * 4];
            uint4 wL = *(const uint4*)&g_w1f[(nt * 2 + 1) * 128 + lane * 4];
            uint32_t bh0[2] = {wH.x, wH.y}, bh1[2] = {wH.z, wH.w};
            uint32_t bl0[2] = {wL.x, wL.y}, bl1[2] = {wL.z, wL.w};
            float2 bl2 = *(const float2*)&b1lin[nt * 8 + (lane & 3) * 2];
#pragma unroll
            for (int t = 0; t < 2; ++t) {
                float ca[4] = {bl2.x, bl2.y, bl2.x, bl2.y};
                float cb[4] = {0.f, 0.f, 0.f, 0.f};
                mma16816h(ca, &aefH[t * 8 + 0], bh0);
                mma16816h(cb, &aefH[t * 8 + 4], bh1);
                mma16816h(ca, &aefL[t * 8 + 0], bh0);
                mma16816h(cb, &aefL[t * 8 + 4], bh1);
                mma16816h(ca, &aefH[t * 8 + 0], bl0);
                mma16816h(cb, &aefH[t * 8 + 4], bl1);
                float v0 = gelu_fast(ca[0] + cb[0]);
                float v1 = gelu_fast(ca[1] + cb[1]);
                float v2 = gelu_fast(ca[2] + cb[2]);
                float v3 = gelu_fast(ca[3] + cb[3]);
                int base = t * 16 + 4 * (nt >> 1) + (nt & 1) * 2;
                aF[base]     = packh2(v0, v1);
                aF[base + 1] = packh2(v2, v3);
            }
        }
    }

    // ---- tmp: lanes 0-15, 16 edges of this warp (bit-exact) ----------------
    {
        const int pbase = wid * 16;
        if (lane < 16) {
            int m = lane >> 1, l = lane & 1;
#pragma unroll 4
            for (int it = 0; it < 16; ++it) {
                int erow = pbase + it;
                int e = e0 + erow;
                int nbr = nidx[e];
                const float* frow = f + (size_t)nbr * 32 + m * 4;
                const float* brow = b1 + (size_t)e * 8;
                float t = 0.f;
#pragma unroll
                for (int d = 0; d < 4; ++d)
                    t = fmaf(frow[d], brow[d * 2 + l], t);
                tmp_s[erow * 16 + lane] = t;
            }
        }
    }
    CPA_WAIT0();       // B0 + bl arrived
    __syncthreads();   // tmp_s complete + cp.async visible to all

    const int er0 = wm * 32 + (lane >> 2);
    const int jq  = (lane & 3) * 2;

    // hoist tmp values (invariant across chunks)
    float tv[16];
#pragma unroll
    for (int rr = 0; rr < 4; ++rr) {
        float2 ta = *(float2*)&tmp_s[(er0 + rr * 8) * 16 + jq];
        float2 tb = *(float2*)&tmp_s[(er0 + rr * 8) * 16 + 8 + jq];
        tv[rr * 4 + 0] = ta.x; tv[rr * 4 + 1] = ta.y;
        tv[rr * 4 + 2] = tb.x; tv[rr * 4 + 3] = tb.y;
    }

    float acc0 = 0.f, acc1 = 0.f, acc2 = 0.f, acc3 = 0.f;

#pragma unroll 1
    for (int ch = 0; ch < 6; ++ch) {
        const uint32_t bufC = (ch & 1) ? (sb + S_B1) : (sb + S_B0);
        const uint32_t bufN = (ch & 1) ? (sb + S_B0) : (sb + S_B1);
        const unsigned char* srcN = g_w2p + (size_t)(ch + 1) * 32768;
        const bool pf = (ch < 5);

#pragma unroll
        for (int nt = 0; nt < 8; ++nt) {
            // spread next-chunk prefetch over nt=0..3 (2 cp.async per thread per nt)
            if (pf && nt < 4) {
                int i0 = tid + 256 * (2 * nt);
                int i1 = tid + 256 * (2 * nt + 1);
                cpa16(bufN + i0 * 16, srcN + i0 * 16);
                cpa16(bufN + i1 * 16, srcN + i1 * 16);
                if (nt == 3) CPA_COMMIT();
            }

            const int nb = wn * 64 + nt * 8;    // col base within chunk
            uint32_t bH[8], bL[8];
            uint32_t rb = (uint32_t)(nb + (lane & 7)) * 128 + ((lane >> 3) << 4);
#pragma unroll
            for (int p = 0; p < 2; ++p) {
                uint32_t off = sw128(rb + 64 * p);
                ldsm_x4(&bH[4 * p], bufC + off);
                ldsm_x4(&bL[4 * p], bufC + 16384 + off);
            }

            // 2 chains (m-tile 0/1); hi+lo accumulate into same acc; bl in init
            const int g0 = ch * 128 + nb + jq;
            float2 blv = *(float2*)&bl_s[g0];
            float c0[4] = {blv.x, blv.y, blv.x, blv.y};
            float c1[4] = {blv.x, blv.y, blv.x, blv.y};
#pragma unroll
            for (int s = 0; s < 4; ++s) {
                mma16816h(c0, &aF[4 * s],      &bH[2 * s]);
                mma16816h(c0, &aF[4 * s],      &bL[2 * s]);
                mma16816h(c1, &aF[16 + 4 * s], &bH[2 * s]);
                mma16816h(c1, &aF[16 + 4 * s], &bL[2 * s]);
            }

            const int sel = (nt & 1) << 1;
            acc0 += c0[0] * tv[sel]      + c0[1] * tv[sel + 1];
            acc1 += c0[2] * tv[4 + sel]  + c0[3] * tv[4 + sel + 1];
            acc2 += c1[0] * tv[8 + sel]  + c1[1] * tv[8 + sel + 1];
            acc3 += c1[2] * tv[12 + sel] + c1[3] * tv[12 + sel + 1];

            if (nt & 1) {
                acc0 += __shfl_xor_sync(0xffffffffu, acc0, 1);
                acc0 += __shfl_xor_sync(0xffffffffu, acc0, 2);
                acc1 += __shfl_xor_sync(0xffffffffu, acc1, 1);
                acc1 += __shfl_xor_sync(0xffffffffu, acc1, 2);
                acc2 += __shfl_xor_sync(0xffffffffu, acc2, 1);
                acc2 += __shfl_xor_sync(0xffffffffu, acc2, 2);
                acc3 += __shfl_xor_sync(0xffffffffu, acc3, 1);
                acc3 += __shfl_xor_sync(0xffffffffu, acc3, 2);
                if ((lane & 3) == 0) {
                    int i = ch * 8 + wn * 4 + (nt >> 1);
                    out_s[er0 * 49 + i]        = acc0;
                    out_s[(er0 + 8) * 49 + i]  = acc1;
                    out_s[(er0 + 16) * 49 + i] = acc2;
                    out_s[(er0 + 24) * 49 + i] = acc3;
                }
                acc0 = 0.f; acc1 = 0.f; acc2 = 0.f; acc3 = 0.f;
            }
        }

        if (pf) {
            CPA_WAIT0();
            __syncthreads();
        }
    }
    __syncthreads();   // out_s complete; B buffers dead -> sc_s/v_s overlay

    // ---- per-edge: qkv = out48.reshape(24,2) @ b2f -> scores + v (to smem) ----
    float* sc_s = (float*)(smem + SV_SC);
    float* v_s  = (float*)(smem + SV_V);
    if (tid < 128) {
        int e = e0 + tid;
        const float* o48 = out_s + tid * 49;
        float bb[8];
#pragma unroll
        for (int x = 0; x < 8; ++x) bb[x] = b2[(size_t)e * 8 + x];

#pragma unroll
        for (int h = 0; h < 4; ++h) {
            float s = 0.f;
#pragma unroll
            for (int mm = 0; mm < 2; ++mm) {
                int m = 2 * h + mm;
#pragma unroll
                for (int d = 0; d < 4; ++d) {
                    float q = o48[m * 2]       * bb[d] + o48[m * 2 + 1]       * bb[4 + d];
                    float k = o48[(8 + m) * 2] * bb[d] + o48[(8 + m) * 2 + 1] * bb[4 + d];
                    s = fmaf(q, k, s);
                }
            }
            sc_s[tid * 4 + h] = s * 0.35355339059327376f;
        }
#pragma unroll
        for (int m = 0; m < 8; ++m)
#pragma unroll
            for (int d = 0; d < 4; ++d)
                v_s[tid * 32 + m * 4 + d] =
                    o48[(16 + m) * 2] * bb[d] + o48[(16 + m) * 2 + 1] * bb[4 + d];
    }
    __syncthreads();

    // ---- per-node attention: warp wid handles node blockIdx.x*8 + wid ----
    {
        float* outsm = (float*)(smem + S_TMP) + wid * 33;   // overlay on tmp_s
        int n = blockIdx.x * 8 + wid;
        int nb = wid * 16;

        float2 sc2 = *(float2*)&sc_s[nb * 4 + lane * 2];
        float s0 = sc2.x, s1 = sc2.y;

        float m0 = s0, m1 = s1;
#pragma unroll
        for (int off = 2; off < 32; off <<= 1) {
            m0 = fmaxf(m0, __shfl_xor_sync(0xffffffffu, m0, off));
            m1 = fmaxf(m1, __shfl_xor_sync(0xffffffffu, m1, off));
        }
        float e0v = expf(s0 - m0), e1v = expf(s1 - m1);
        float z0 = e0v, z1 = e1v;
#pragma unroll
        for (int off = 2; off < 32; off <<= 1) {
            z0 += __shfl_xor_sync(0xffffffffu, z0, off);
            z1 += __shfl_xor_sync(0xffffffffu, z1, off);
        }
        float a0 = e0v / z0, a1 = e1v / z1;

        const int m_mine = lane & 7;
        const int hsel   = (m_mine >> 1) & 1;
        float r[4] = {0.f, 0.f, 0.f, 0.f};
#pragma unroll
        for (int it = 0; it < 4; ++it) {
            float4 vv = *(float4*)&v_s[nb * 32 + it * 128 + lane * 4];
            int lsrc = 8 * it + ((lane >> 3) << 1) + ((lane >> 2) & 1);
            float av0 = __shfl_sync(0xffffffffu, a0, lsrc);
            float av1 = __shfl_sync(0xffffffffu, a1, lsrc);
            float a = hsel ? av1 : av0;
            r[0] = fmaf(a, vv.x, r[0]);
            r[1] = fmaf(a, vv.y, r[1]);
            r[2] = fmaf(a, vv.z, r[2]);
            r[3] = fmaf(a, vv.w, r[3]);
        }
#pragma unroll
        for (int off = 8; off < 32; off <<= 1)
#pragma unroll
            for (int d = 0; d < 4; ++d)
                r[d] += __shfl_xor_sync(0xffffffffu, r[d], off);

        if (lane < 8) {
#pragma unroll
            for (int d = 0; d < 4; ++d)
                outsm[m_mine * 4 + d] = r[d];
        }
        __syncwarp();

        int mm = lane >> 2, dd = lane & 3;
        int o = (dd == 0) ? mm : 8 + mm;
        float val = (dd == 0) ? bias[mm] : 0.f;
#pragma unroll
        for (int mp = 0; mp < 8; ++mp)
            val = fmaf(Wout[o * 8 + mp], outsm[mp * 4 + dd], val);
        out[(size_t)n * 32 + lane] = val;
    }
}

// ---------------- launcher ----------------------------------------------------
extern "C" void kernel_launch(void* const* d_in, const int* in_sizes, int n_in,
                              void* d_out, int out_size) {
    const float* b1   = (const float*)d_in[0];
    const float* b2   = (const float*)d_in[1];
    const float* ef   = (const float*)d_in[2];
    const float* f    = (const float*)d_in[3];
    const int*   nidx = (const int*)  d_in[4];
    const float* W1   = (const float*)d_in[5];
    const float* b1l  = (const float*)d_in[6];
    const float* W2   = (const float*)d_in[7];
    const float* b2l  = (const float*)d_in[8];
    const float* Wout = (const float*)d_in[9];
    const float* bias = (const float*)d_in[10];
    float* out = (float*)d_out;
    (void)in_sizes; (void)n_in; (void)out_size;

    cudaFuncSetAttribute(k2_fused, cudaFuncAttributeMaxDynamicSharedMemorySize, S_TOT);

    k0_prep<<<(768 * 64 + 255) / 256, 256>>>(W2, W1);
    k2_fused<<<NTILES, 256, S_TOT>>>(ef, b1l, f, nidx, b1, b2, b2l, Wout, bias, out);
}